// round 5
// baseline (speedup 1.0000x reference)
#include <cuda_runtime.h>
#include <cuda_bf16.h>

// out[n] = dot(inputs[n, 0:272], weights) + bias
// weights[0:16]  = kernel
// weights[16+x]  = k[4a1+a2]*k[4b1+b2]*w1 + k[4a1+b2]*k[4b1+a2]*w2
//
// HBM-bound stream (544 MB read once). Persistent, residency-exact grid.
// Software-pipelined: each warp processes 2 rows/iter, with the NEXT
// iteration's 5 LDG.128 issued before the current FMA/reduce/store, so
// global loads are in flight continuously (no duty-cycle gaps).

#define UNITS 16
#define D 272            // floats per row
#define D4 68            // float4 per row
#define WARPS_PER_BLOCK 8
#define THREADS (WARPS_PER_BLOCK * 32)
#define ROWS_PER_WARP 2
#define ROWS_PER_BLOCK (WARPS_PER_BLOCK * ROWS_PER_WARP)   // 16

__device__ __forceinline__ float4 ldcs4(const float4* p) { return __ldcs(p); }

struct Buf {
    float4 a00, a01, a10, a11, at;
};

__device__ __forceinline__ void load_pair(Buf& b, const float4* __restrict__ in4,
                                          long long row, int lane)
{
    const float4* r0 = in4 + row * D4;
    const float4* r1 = r0 + D4;
    b.a00 = ldcs4(r0 + lane);
    b.a01 = ldcs4(r0 + lane + 32);
    b.a10 = ldcs4(r1 + lane);
    b.a11 = ldcs4(r1 + lane + 32);
    // Tail float4 64..67: lanes 0-3 -> row0, lanes 4-7 -> row1.
    if (lane < 8)
        b.at = ldcs4(in4 + (row + (lane >> 2)) * D4 + 64 + (lane & 3));
    else
        b.at = make_float4(0.f, 0.f, 0.f, 0.f);
}

__global__ __launch_bounds__(THREADS)
void linear_gemv_kernel(const float* __restrict__ in,
                        const float* __restrict__ kern,
                        const float* __restrict__ w1p,
                        const float* __restrict__ w2p,
                        const float* __restrict__ biasp,
                        float* __restrict__ out,
                        int n)
{
    __shared__ __align__(16) float w[D];

    const int tid = threadIdx.x;

    // Build the 272-float weight vector once per block.
    if (tid < UNITS) {
        w[tid] = kern[tid];
    }
    if (tid < 256) {
        const float w1 = *w1p;
        const float w2 = *w2p;
        const int x1 = tid >> 4;
        const int x2 = tid & 15;
        const int a1 = x1 >> 2, b1 = x1 & 3;
        const int a2 = x2 >> 2, b2 = x2 & 3;
        w[UNITS + tid] = kern[4 * a1 + a2] * kern[4 * b1 + b2] * w1
                       + kern[4 * a1 + b2] * kern[4 * b1 + a2] * w2;
    }
    __syncthreads();

    const float bias = *biasp;
    const int lane = tid & 31;
    const int warp = tid >> 5;

    // Loop-invariant weights in registers.
    const float4* __restrict__ wp = (const float4*)w;
    const float4 b0 = wp[lane];
    const float4 b1 = wp[lane + 32];
    float4 bt = make_float4(0.f, 0.f, 0.f, 0.f);
    if (lane < 8) bt = wp[64 + (lane & 3)];

    const float4* __restrict__ in4 = (const float4*)in;

    const long long stride = (long long)gridDim.x * ROWS_PER_BLOCK;
    long long row = ((long long)blockIdx.x * WARPS_PER_BLOCK + warp) * ROWS_PER_WARP;

    bool valid = (row + 1) < (long long)n;

    Buf cur;
    if (valid) load_pair(cur, in4, row, lane);    // prologue prefetch

    while (valid) {
        const long long nrow = row + stride;
        const bool nvalid = (nrow + 1) < (long long)n;

        // ---- Prefetch next iteration BEFORE consuming current ----
        Buf nxt;
        if (nvalid) load_pair(nxt, in4, nrow, lane);

        // ---- Consume current ----
        float s0 = 0.f, s1 = 0.f;
        s0 = fmaf(cur.a00.x, b0.x, s0); s0 = fmaf(cur.a00.y, b0.y, s0);
        s0 = fmaf(cur.a00.z, b0.z, s0); s0 = fmaf(cur.a00.w, b0.w, s0);
        s0 = fmaf(cur.a01.x, b1.x, s0); s0 = fmaf(cur.a01.y, b1.y, s0);
        s0 = fmaf(cur.a01.z, b1.z, s0); s0 = fmaf(cur.a01.w, b1.w, s0);

        s1 = fmaf(cur.a10.x, b0.x, s1); s1 = fmaf(cur.a10.y, b0.y, s1);
        s1 = fmaf(cur.a10.z, b0.z, s1); s1 = fmaf(cur.a10.w, b0.w, s1);
        s1 = fmaf(cur.a11.x, b1.x, s1); s1 = fmaf(cur.a11.y, b1.y, s1);
        s1 = fmaf(cur.a11.z, b1.z, s1); s1 = fmaf(cur.a11.w, b1.w, s1);

        const float ts = fmaf(cur.at.x, bt.x,
                         fmaf(cur.at.y, bt.y,
                         fmaf(cur.at.z, bt.z, cur.at.w * bt.w)));
        if (lane < 4)       s0 += ts;
        else if (lane < 8)  s1 += ts;

        #pragma unroll
        for (int off = 16; off > 0; off >>= 1) {
            s0 += __shfl_xor_sync(0xFFFFFFFFu, s0, off);
            s1 += __shfl_xor_sync(0xFFFFFFFFu, s1, off);
        }

        if (lane == 0)
            *(float2*)(out + row) = make_float2(s0 + bias, s1 + bias);

        cur = nxt;
        row = nrow;
        valid = nvalid;
    }

    // Odd-n remainder (cold; n=500000 is even): last single row.
    if ((n & 1) && blockIdx.x == 0 && warp == 0) {
        const long long r = n - 1;
        const float4* rp = in4 + r * D4;
        float s = 0.f;
        float4 a = ldcs4(rp + lane);
        s = fmaf(a.x, b0.x, s); s = fmaf(a.y, b0.y, s);
        s = fmaf(a.z, b0.z, s); s = fmaf(a.w, b0.w, s);
        a = ldcs4(rp + lane + 32);
        s = fmaf(a.x, b1.x, s); s = fmaf(a.y, b1.y, s);
        s = fmaf(a.z, b1.z, s); s = fmaf(a.w, b1.w, s);
        if (lane < 4) {
            float4 t = ldcs4(rp + 64 + lane);
            float4 bw = wp[64 + lane];
            s = fmaf(t.x, bw.x, s); s = fmaf(t.y, bw.y, s);
            s = fmaf(t.z, bw.z, s); s = fmaf(t.w, bw.w, s);
        }
        #pragma unroll
        for (int off = 16; off > 0; off >>= 1)
            s += __shfl_xor_sync(0xFFFFFFFFu, s, off);
        if (lane == 0) out[r] = s + bias;
    }
}

extern "C" void kernel_launch(void* const* d_in, const int* in_sizes, int n_in,
                              void* d_out, int out_size)
{
    const float* in   = (const float*)d_in[0];   // [N, 272]
    const float* kern = (const float*)d_in[1];   // [16]
    const float* w1   = (const float*)d_in[2];   // [1]
    const float* w2   = (const float*)d_in[3];   // [1]
    const float* bias = (const float*)d_in[4];   // [1]
    float* out = (float*)d_out;

    const int n = out_size;  // 500000 rows

    // Residency-exact persistent grid: exactly one wave, no tail imbalance.
    int per_sm = 0;
    cudaOccupancyMaxActiveBlocksPerMultiprocessor(&per_sm, linear_gemv_kernel,
                                                  THREADS, 0);
    if (per_sm < 1) per_sm = 1;
    int sms = 148;
    cudaDeviceGetAttribute(&sms, cudaDevAttrMultiProcessorCount, 0);

    int blocks = per_sm * sms;
    const int blocks_needed = (n + ROWS_PER_BLOCK - 1) / ROWS_PER_BLOCK;
    if (blocks > blocks_needed) blocks = blocks_needed;
    if (blocks < 1) blocks = 1;

    linear_gemv_kernel<<<blocks, THREADS>>>(in, kern, w1, w2, bias, out, n);
}